// round 7
// baseline (speedup 1.0000x reference)
#include <cuda_runtime.h>

// Problem constants (fixed: B=32, D=256, T=2048, K=1024)
#define BVAL 32
#define DVAL 256
#define TVAL 2048
#define KVAL 1024
#define NVAL (BVAL * TVAL)          // 65536 vectors
#define QELEMS (BVAL * DVAL * TVAL) // 16777216 quantized elements
#define NPART (BVAL * (TVAL / 256)) // 256 loss partials

__device__ unsigned long long g_best[NVAL];
__device__ float g_enorm[KVAL];
__device__ float g_xnorm[NVAL];
__device__ float g_partials[NPART];

// Monotone float -> uint mapping (order-preserving incl. negatives)
__device__ __forceinline__ unsigned int ford(float f) {
    unsigned int b = __float_as_uint(f);
    return (b & 0x80000000u) ? ~b : (b | 0x80000000u);
}

__global__ void init_best_kernel() {
    int i = blockIdx.x * blockDim.x + threadIdx.x;
    if (i < NVAL) g_best[i] = ~0ull;
}

// ||e_k||^2 in double, rounded once to fp32 (= fl32(exact))
__global__ void enorm_kernel(const float* __restrict__ E) {
    int warp = threadIdx.x >> 5, lane = threadIdx.x & 31;
    int k = blockIdx.x * 8 + warp;
    if (k >= KVAL) return;
    const float* row = E + (size_t)k * DVAL;
    double s = 0.0;
    for (int d = lane; d < DVAL; d += 32) { double v = (double)row[d]; s += v * v; }
    #pragma unroll
    for (int o = 16; o; o >>= 1) s += __shfl_xor_sync(0xffffffffu, s, o);
    if (lane == 0) g_enorm[k] = (float)s;
}

// ||x_n||^2 per vector (b,t); coalesced over t. Double accum -> fp32.
__global__ void xnorm_kernel(const float* __restrict__ X) {
    int t = blockIdx.x * 256 + threadIdx.x;
    int b = blockIdx.y;
    const float* base = X + (size_t)b * DVAL * TVAL + t;
    double s = 0.0;
    #pragma unroll 8
    for (int d = 0; d < DVAL; d++) { double v = (double)base[(size_t)d * TVAL]; s += v * v; }
    g_xnorm[(size_t)b * TVAL + t] = (float)s;
}

// Distance GEMM + fused argmin, replicating the reference's fp32 rounding:
//   dist = fl32( fl32(sxx + se_k) - 2*m )  with m = fp32 dot (two-level accum).
// Block: 128(k) x 128(t), 256 threads, 8x8 register tile, 32-deep smem tiles.
__global__ __launch_bounds__(256, 1)
void dist_argmin_kernel(const float* __restrict__ X, const float* __restrict__ E) {
    __shared__ float As[32][132];                 // [d][k]
    __shared__ float Bs[32][132];                 // [d][t]
    __shared__ float en[128];
    __shared__ float sxx[128];
    __shared__ unsigned long long red[128][16];

    const int tid = threadIdx.x;
    const int k0 = blockIdx.x * 128;
    const int t0 = blockIdx.y * 128;
    const int b  = blockIdx.z;
    const int tx = tid & 15, ty = tid >> 4;

    if (tid < 128) {
        en[tid]  = g_enorm[k0 + tid];
        sxx[tid] = g_xnorm[(size_t)b * TVAL + t0 + tid];
    }

    float sum[8][8];
    #pragma unroll
    for (int i = 0; i < 8; i++)
        #pragma unroll
        for (int j = 0; j < 8; j++) sum[i][j] = 0.f;

    const float* Xb = X + (size_t)b * DVAL * TVAL;

    for (int d0 = 0; d0 < DVAL; d0 += 32) {
        // E tile: [128k x 32d] -> As[d][k]
        #pragma unroll
        for (int r = 0; r < 16; r++) {
            int li = r * 256 + tid;
            int kk = li >> 5, dd = li & 31;
            As[dd][kk] = E[(size_t)(k0 + kk) * DVAL + d0 + dd];
        }
        // X tile: [32d x 128t] -> Bs[d][t]
        #pragma unroll
        for (int r = 0; r < 16; r++) {
            int li = r * 256 + tid;
            int dd = li >> 7, tl = li & 127;
            Bs[dd][tl] = Xb[(size_t)(d0 + dd) * TVAL + t0 + tl];
        }
        __syncthreads();

        // 32-term chunk in acc (first accumulation level)
        float acc[8][8];
        #pragma unroll
        for (int i = 0; i < 8; i++)
            #pragma unroll
            for (int j = 0; j < 8; j++) acc[i][j] = 0.f;

        #pragma unroll
        for (int d = 0; d < 32; d++) {
            float4 a0 = *(const float4*)&As[d][ty * 8];
            float4 a1 = *(const float4*)&As[d][ty * 8 + 4];
            float4 b0 = *(const float4*)&Bs[d][tx * 8];
            float4 b1 = *(const float4*)&Bs[d][tx * 8 + 4];
            float a[8]  = {a0.x, a0.y, a0.z, a0.w, a1.x, a1.y, a1.z, a1.w};
            float bb[8] = {b0.x, b0.y, b0.z, b0.w, b1.x, b1.y, b1.z, b1.w};
            #pragma unroll
            for (int i = 0; i < 8; i++)
                #pragma unroll
                for (int j = 0; j < 8; j++) acc[i][j] += a[i] * bb[j];
        }
        // fold chunk into second level
        #pragma unroll
        for (int i = 0; i < 8; i++)
            #pragma unroll
            for (int j = 0; j < 8; j++) sum[i][j] += acc[i][j];
        __syncthreads();
    }

    // Epilogue: dist with reference-matching rounding, argmin w/ index tiebreak
    #pragma unroll
    for (int j = 0; j < 8; j++) {
        float sx = sxx[tx * 8 + j];
        unsigned long long m = ~0ull;
        #pragma unroll
        for (int i = 0; i < 8; i++) {
            float s    = __fadd_rn(sx, en[ty * 8 + i]);      // fl32(sxx + se)
            float dist = __fmaf_rn(-2.0f, sum[i][j], s);     // fl32(s - 2m), 2m exact
            unsigned long long key =
                ((unsigned long long)ford(dist) << 32) | (unsigned)(k0 + ty * 8 + i);
            m = (key < m) ? key : m;
        }
        red[tx * 8 + j][ty] = m;
    }
    __syncthreads();

    if (tid < 128) {
        unsigned long long m = red[tid][0];
        #pragma unroll
        for (int y = 1; y < 16; y++) {
            unsigned long long v = red[tid][y];
            m = (v < m) ? v : m;
        }
        atomicMin(&g_best[(size_t)b * TVAL + t0 + tid], m);
    }
}

// Gather + straight-through output + indices + loss partials
__global__ void gather_out_kernel(const float* __restrict__ X,
                                  const float* __restrict__ E,
                                  float* __restrict__ out) {
    const int tid = threadIdx.x;
    const int b = blockIdx.y;
    const int t = blockIdx.x * 256 + tid;

    unsigned long long pk = g_best[(size_t)b * TVAL + t];
    int idx = (int)(unsigned)(pk & 0xffffffffu);
    const float* erow = E + (size_t)idx * DVAL;

    float s = 0.f;
    size_t base = (size_t)b * DVAL * TVAL + t;
    for (int d = 0; d < DVAL; d++) {
        float q  = erow[d];
        float xv = X[base + (size_t)d * TVAL];
        float diff = __fadd_rn(q, -xv);                       // fl32(q - x)
        out[base + (size_t)d * TVAL] = __fadd_rn(xv, diff);   // fl32(x + (q - x))
        s += diff * diff;
    }
    out[(size_t)QELEMS + 1 + (size_t)b * TVAL + t] = (float)idx;

    __shared__ float r[256];
    r[tid] = s;
    __syncthreads();
    #pragma unroll
    for (int o = 128; o; o >>= 1) {
        if (tid < o) r[tid] += r[tid + o];
        __syncthreads();
    }
    if (tid == 0) g_partials[blockIdx.y * (TVAL / 256) + blockIdx.x] = r[0];
}

__global__ void finalize_kernel(float* __restrict__ out) {
    __shared__ float r[256];
    int tid = threadIdx.x;
    r[tid] = g_partials[tid];
    __syncthreads();
    #pragma unroll
    for (int o = 128; o; o >>= 1) {
        if (tid < o) r[tid] += r[tid + o];
        __syncthreads();
    }
    if (tid == 0) out[QELEMS] = 1.25f * (r[0] / (float)QELEMS);
}

extern "C" void kernel_launch(void* const* d_in, const int* in_sizes, int n_in,
                              void* d_out, int out_size) {
    const float* X = (const float*)d_in[0];  // inputs [B, D, T] fp32
    const float* E = (const float*)d_in[1];  // embeddings [K, D] fp32
    float* out = (float*)d_out;              // [quantized | loss | indices] fp32

    init_best_kernel<<<NVAL / 256, 256>>>();
    enorm_kernel<<<KVAL / 8, 256>>>(E);
    xnorm_kernel<<<dim3(TVAL / 256, BVAL), 256>>>(X);
    dist_argmin_kernel<<<dim3(KVAL / 128, TVAL / 128, BVAL), 256>>>(X, E);
    gather_out_kernel<<<dim3(TVAL / 256, BVAL), 256>>>(X, E, out);
    finalize_kernel<<<1, 256>>>(out);
}

// round 8
// speedup vs baseline: 1.0124x; 1.0124x over previous
#include <cuda_runtime.h>

// Problem constants (fixed: B=32, D=256, T=2048, K=1024)
#define BVAL 32
#define DVAL 256
#define TVAL 2048
#define KVAL 1024
#define NVAL (BVAL * TVAL)          // 65536 vectors
#define QELEMS (BVAL * DVAL * TVAL) // 16777216 quantized elements
#define NPART (BVAL * (TVAL / 256)) // 256 loss partials

__device__ unsigned long long g_best[NVAL];
__device__ float g_enorm[KVAL];
__device__ float g_xnorm[NVAL];
__device__ float g_partials[NPART];

// ---- packed f32x2 helpers (per-lane IEEE fp32, bit-identical to scalar FFMA) ----
__device__ __forceinline__ unsigned long long pack2_dup(float x) {
    unsigned long long r;
    asm("mov.b64 %0, {%1, %1};" : "=l"(r) : "r"(__float_as_uint(x)));
    return r;
}
__device__ __forceinline__ void ffma2(unsigned long long &c, unsigned long long a,
                                      unsigned long long b) {
    asm("fma.rn.f32x2 %0, %1, %2, %0;" : "+l"(c) : "l"(a), "l"(b));
}
__device__ __forceinline__ unsigned long long add2(unsigned long long a,
                                                   unsigned long long b) {
    unsigned long long d;
    asm("add.rn.f32x2 %0, %1, %2;" : "=l"(d) : "l"(a), "l"(b));
    return d;
}
__device__ __forceinline__ float2 unpack2(unsigned long long p) {
    unsigned int lo, hi;
    asm("mov.b64 {%0, %1}, %2;" : "=r"(lo), "=r"(hi) : "l"(p));
    return make_float2(__uint_as_float(lo), __uint_as_float(hi));
}

// Monotone float -> uint mapping (order-preserving incl. negatives)
__device__ __forceinline__ unsigned int ford(float f) {
    unsigned int b = __float_as_uint(f);
    return (b & 0x80000000u) ? ~b : (b | 0x80000000u);
}

// ||e_k||^2 in double, rounded once to fp32 (= fl32(exact))
__global__ void enorm_kernel(const float* __restrict__ E) {
    int warp = threadIdx.x >> 5, lane = threadIdx.x & 31;
    int k = blockIdx.x * 8 + warp;
    if (k >= KVAL) return;
    const float* row = E + (size_t)k * DVAL;
    double s = 0.0;
    for (int d = lane; d < DVAL; d += 32) { double v = (double)row[d]; s += v * v; }
    #pragma unroll
    for (int o = 16; o; o >>= 1) s += __shfl_xor_sync(0xffffffffu, s, o);
    if (lane == 0) g_enorm[k] = (float)s;
}

// ||x_n||^2 per vector; also initializes g_best (fused init).
__global__ void xnorm_kernel(const float* __restrict__ X) {
    int t = blockIdx.x * 256 + threadIdx.x;
    int b = blockIdx.y;
    const float* base = X + (size_t)b * DVAL * TVAL + t;
    double s = 0.0;
    #pragma unroll 8
    for (int d = 0; d < DVAL; d++) { double v = (double)base[(size_t)d * TVAL]; s += v * v; }
    size_t n = (size_t)b * TVAL + t;
    g_xnorm[n] = (float)s;
    g_best[n] = ~0ull;
}

// Distance GEMM + fused argmin. Bit-identical math to the passing scalar
// kernel: dist = fl32( fl32(sxx + se_k) - 2*m ), m = fp32 dot with two-level
// (32-term chunk) accumulation in the same order; FFMA2 pairs lanes along t
// but each (k,t) chain keeps its exact scalar order/rounding.
__global__ __launch_bounds__(256, 1)
void dist_argmin_kernel(const float* __restrict__ X, const float* __restrict__ E) {
    __shared__ float As[32][132];                 // [d][k]
    __shared__ float Bs[32][132];                 // [d][t]
    __shared__ float en[128];
    __shared__ float sxx[128];
    __shared__ unsigned long long red[128][16];

    const int tid = threadIdx.x;
    const int k0 = blockIdx.x * 128;
    const int t0 = blockIdx.y * 128;
    const int b  = blockIdx.z;
    const int tx = tid & 15, ty = tid >> 4;

    if (tid < 128) {
        en[tid]  = g_enorm[k0 + tid];
        sxx[tid] = g_xnorm[(size_t)b * TVAL + t0 + tid];
    }

    unsigned long long sum2[8][4];                // [k][t-pair] second level
    #pragma unroll
    for (int i = 0; i < 8; i++)
        #pragma unroll
        for (int jp = 0; jp < 4; jp++) sum2[i][jp] = 0ull;

    const float* Xb = X + (size_t)b * DVAL * TVAL;

    for (int d0 = 0; d0 < DVAL; d0 += 32) {
        // E tile: [128k x 32d] -> As[d][k]
        #pragma unroll
        for (int r = 0; r < 16; r++) {
            int li = r * 256 + tid;
            int kk = li >> 5, dd = li & 31;
            As[dd][kk] = E[(size_t)(k0 + kk) * DVAL + d0 + dd];
        }
        // X tile: [32d x 128t] -> Bs[d][t]
        #pragma unroll
        for (int r = 0; r < 16; r++) {
            int li = r * 256 + tid;
            int dd = li >> 7, tl = li & 127;
            Bs[dd][tl] = Xb[(size_t)(d0 + dd) * TVAL + t0 + tl];
        }
        __syncthreads();

        unsigned long long acc2[8][4];            // first-level 32-term chunk
        #pragma unroll
        for (int i = 0; i < 8; i++)
            #pragma unroll
            for (int jp = 0; jp < 4; jp++) acc2[i][jp] = 0ull;

        #pragma unroll
        for (int d = 0; d < 32; d++) {
            // b pairs load naturally as 64-bit lanes (little-endian: lo = lower t)
            ulonglong2 bA = *(const ulonglong2*)&Bs[d][tx * 8];
            ulonglong2 bB = *(const ulonglong2*)&Bs[d][tx * 8 + 4];
            unsigned long long b2[4] = {bA.x, bA.y, bB.x, bB.y};

            float4 a0 = *(const float4*)&As[d][ty * 8];
            float4 a1 = *(const float4*)&As[d][ty * 8 + 4];
            unsigned long long a2[8] = {
                pack2_dup(a0.x), pack2_dup(a0.y), pack2_dup(a0.z), pack2_dup(a0.w),
                pack2_dup(a1.x), pack2_dup(a1.y), pack2_dup(a1.z), pack2_dup(a1.w)};

            #pragma unroll
            for (int i = 0; i < 8; i++)
                #pragma unroll
                for (int jp = 0; jp < 4; jp++) ffma2(acc2[i][jp], a2[i], b2[jp]);
        }
        // fold chunk into second level (lane-wise add, same order as scalar)
        #pragma unroll
        for (int i = 0; i < 8; i++)
            #pragma unroll
            for (int jp = 0; jp < 4; jp++) sum2[i][jp] = add2(sum2[i][jp], acc2[i][jp]);
        __syncthreads();
    }

    // Unpack and run the identical epilogue
    float sum[8][8];
    #pragma unroll
    for (int i = 0; i < 8; i++)
        #pragma unroll
        for (int jp = 0; jp < 4; jp++) {
            float2 v = unpack2(sum2[i][jp]);
            sum[i][2 * jp]     = v.x;
            sum[i][2 * jp + 1] = v.y;
        }

    #pragma unroll
    for (int j = 0; j < 8; j++) {
        float sx = sxx[tx * 8 + j];
        unsigned long long m = ~0ull;
        #pragma unroll
        for (int i = 0; i < 8; i++) {
            float s    = __fadd_rn(sx, en[ty * 8 + i]);      // fl32(sxx + se)
            float dist = __fmaf_rn(-2.0f, sum[i][j], s);     // fl32(s - 2m)
            unsigned long long key =
                ((unsigned long long)ford(dist) << 32) | (unsigned)(k0 + ty * 8 + i);
            m = (key < m) ? key : m;
        }
        red[tx * 8 + j][ty] = m;
    }
    __syncthreads();

    if (tid < 128) {
        unsigned long long m = red[tid][0];
        #pragma unroll
        for (int y = 1; y < 16; y++) {
            unsigned long long v = red[tid][y];
            m = (v < m) ? v : m;
        }
        atomicMin(&g_best[(size_t)b * TVAL + t0 + tid], m);
    }
}

// Gather + straight-through output + indices + loss partials
__global__ void gather_out_kernel(const float* __restrict__ X,
                                  const float* __restrict__ E,
                                  float* __restrict__ out) {
    const int tid = threadIdx.x;
    const int b = blockIdx.y;
    const int t = blockIdx.x * 256 + tid;

    unsigned long long pk = g_best[(size_t)b * TVAL + t];
    int idx = (int)(unsigned)(pk & 0xffffffffu);
    const float* erow = E + (size_t)idx * DVAL;

    float s = 0.f;
    size_t base = (size_t)b * DVAL * TVAL + t;
    for (int d = 0; d < DVAL; d++) {
        float q  = erow[d];
        float xv = X[base + (size_t)d * TVAL];
        float diff = __fadd_rn(q, -xv);                       // fl32(q - x)
        out[base + (size_t)d * TVAL] = __fadd_rn(xv, diff);   // fl32(x + (q - x))
        s += diff * diff;
    }
    out[(size_t)QELEMS + 1 + (size_t)b * TVAL + t] = (float)idx;

    __shared__ float r[256];
    r[tid] = s;
    __syncthreads();
    #pragma unroll
    for (int o = 128; o; o >>= 1) {
        if (tid < o) r[tid] += r[tid + o];
        __syncthreads();
    }
    if (tid == 0) g_partials[blockIdx.y * (TVAL / 256) + blockIdx.x] = r[0];
}

__global__ void finalize_kernel(float* __restrict__ out) {
    __shared__ float r[256];
    int tid = threadIdx.x;
    r[tid] = g_partials[tid];
    __syncthreads();
    #pragma unroll
    for (int o = 128; o; o >>= 1) {
        if (tid < o) r[tid] += r[tid + o];
        __syncthreads();
    }
    if (tid == 0) out[QELEMS] = 1.25f * (r[0] / (float)QELEMS);
}

extern "C" void kernel_launch(void* const* d_in, const int* in_sizes, int n_in,
                              void* d_out, int out_size) {
    const float* X = (const float*)d_in[0];  // inputs [B, D, T] fp32
    const float* E = (const float*)d_in[1];  // embeddings [K, D] fp32
    float* out = (float*)d_out;              // [quantized | loss | indices] fp32

    enorm_kernel<<<KVAL / 8, 256>>>(E);
    xnorm_kernel<<<dim3(TVAL / 256, BVAL), 256>>>(X);
    dist_argmin_kernel<<<dim3(KVAL / 128, TVAL / 128, BVAL), 256>>>(X, E);
    gather_out_kernel<<<dim3(TVAL / 256, BVAL), 256>>>(X, E, out);
    finalize_kernel<<<1, 256>>>(out);
}

// round 12
// speedup vs baseline: 1.5828x; 1.5634x over previous
#include <cuda_runtime.h>
#include <cuda_fp16.h>
#include <cstdint>

// Problem constants (fixed: B=32, D=256, T=2048, K=1024)
#define BVAL 32
#define DVAL 256
#define TVAL 2048
#define KVAL 1024
#define NVAL (BVAL * TVAL)          // 65536 vectors
#define QELEMS (BVAL * DVAL * TVAL) // 16777216 quantized elements
#define NPART (BVAL * (TVAL / 256)) // 256 loss partials
#define KTILES (KVAL / 128)         // 8

typedef unsigned long long u64;

__device__ float g_enorm[KVAL];
__device__ float g_xnorm[NVAL];
__device__ float g_partials[NPART];
__device__ u64   g_cand[(size_t)NVAL * 16]; // [row][ktile(8)][2]
__device__ int   g_idx[NVAL];
// Pre-split operands (halves). X transposed to [B][T][D] (d-contiguous).
__device__ __half g_Xh[QELEMS];
__device__ __half g_Xl[QELEMS];
__device__ __half g_Eh[KVAL * DVAL];
__device__ __half g_El[KVAL * DVAL];

// dist = s - 2*(M/1024) = fmaf(-2^-9, M, s), since E was scaled by 1024
#define NEG2POW9 (-0.001953125f)

__device__ __forceinline__ unsigned int ford(float f) {
    unsigned int b = __float_as_uint(f);
    return (b & 0x80000000u) ? ~b : (b | 0x80000000u);
}
__device__ __forceinline__ uint32_t smem_u32(const void* p) {
    uint32_t a;
    asm("{ .reg .u64 t; cvta.to.shared.u64 t, %1; cvt.u32.u64 %0, t; }"
        : "=r"(a) : "l"(p));
    return a;
}
__device__ __forceinline__ void ldsm4(uint32_t* r, uint32_t addr) {
    asm volatile("ldmatrix.sync.aligned.m8n8.x4.shared.b16 {%0,%1,%2,%3}, [%4];"
                 : "=r"(r[0]), "=r"(r[1]), "=r"(r[2]), "=r"(r[3]) : "r"(addr));
}
#define MMA16816(d, a, b0, b1)                                                \
    asm volatile("mma.sync.aligned.m16n8k16.row.col.f32.f16.f16.f32 "         \
                 "{%0,%1,%2,%3},{%4,%5,%6,%7},{%8,%9},{%0,%1,%2,%3};"         \
                 : "+f"((d)[0]), "+f"((d)[1]), "+f"((d)[2]), "+f"((d)[3])     \
                 : "r"((a)[0]), "r"((a)[1]), "r"((a)[2]), "r"((a)[3]),        \
                   "r"(b0), "r"(b1))

// ---------------- prep: split E (scaled by 1024) into hi/lo halves ----------
__global__ void prep_e_kernel(const float* __restrict__ E) {
    int i = blockIdx.x * 256 + threadIdx.x;
    float e = E[i] * 1024.0f;                 // exact pow2 scale
    __half h = __float2half_rn(e);
    g_Eh[i] = h;
    g_El[i] = __float2half_rn(e - __half2float(h));
}

// ---------------- prep: transpose X to [B][T][D] and split hi/lo ------------
__global__ void prep_x_kernel(const float* __restrict__ X) {
    __shared__ float tile[32][33];
    const int b = blockIdx.z, d0 = blockIdx.y * 32, t0 = blockIdx.x * 32;
    const int tx = threadIdx.x, ty = threadIdx.y;  // (32, 8)
    #pragma unroll
    for (int r = 0; r < 4; r++) {
        int d = r * 8 + ty;
        tile[d][tx] = X[(size_t)b * DVAL * TVAL + (size_t)(d0 + d) * TVAL + t0 + tx];
    }
    __syncthreads();
    #pragma unroll
    for (int r = 0; r < 4; r++) {
        int t = r * 8 + ty;
        float v = tile[tx][t];                 // tx indexes d now
        __half h = __float2half_rn(v);
        size_t o = ((size_t)b * TVAL + t0 + t) * DVAL + d0 + tx;
        g_Xh[o] = h;
        g_Xl[o] = __float2half_rn(v - __half2float(h));
    }
}

// ||e_k||^2 exact (double accum -> fp32)
__global__ void enorm_kernel(const float* __restrict__ E) {
    int warp = threadIdx.x >> 5, lane = threadIdx.x & 31;
    int k = blockIdx.x * 8 + warp;
    if (k >= KVAL) return;
    const float* row = E + (size_t)k * DVAL;
    double s = 0.0;
    for (int d = lane; d < DVAL; d += 32) { double v = (double)row[d]; s += v * v; }
    #pragma unroll
    for (int o = 16; o; o >>= 1) s += __shfl_xor_sync(0xffffffffu, s, o);
    if (lane == 0) g_enorm[k] = (float)s;
}

// ||x_n||^2 per vector
__global__ void xnorm_kernel(const float* __restrict__ X) {
    int t = blockIdx.x * 256 + threadIdx.x;
    int b = blockIdx.y;
    const float* base = X + (size_t)b * DVAL * TVAL + t;
    double s = 0.0;
    #pragma unroll 8
    for (int d = 0; d < DVAL; d++) { double v = (double)base[(size_t)d * TVAL]; s += v * v; }
    g_xnorm[(size_t)b * TVAL + t] = (float)s;
}

// ---------------- distance GEMM via mma.sync (HMMA) + top-2 epilogue -------
// CTA tile: 128 t x 128 k, D in 16 chunks of 16. 8 warps: tw=wid&3 (t-group
// of 32 rows), kw=wid>>2 (k-group of 64 cols). Warp tile 32x64 via
// m16n8k16: 2 m-tiles x 8 n-tiles, 4 split passes (hh,hl,lh,ll) -> fp32 acc.
__global__ __launch_bounds__(256, 2)
void dist_tc_kernel() {
    __shared__ __align__(128) char sbuf[2][16384]; // per buf: Ah|Al|Bh|Bl (4KB each)
    __shared__ float en_sm[128];
    __shared__ u64 cand_sm[128][2][2];

    const int tid = threadIdx.x, wid = tid >> 5, l = tid & 31;
    const int tw = wid & 3, kw = wid >> 2;
    const int k0 = blockIdx.x * 128, t0 = blockIdx.y * 128, b = blockIdx.z;

    if (tid < 128) en_sm[tid] = g_enorm[k0 + tid];

    float acc[2][8][4];
    #pragma unroll
    for (int i = 0; i < 2; i++)
        #pragma unroll
        for (int j = 0; j < 8; j++)
            #pragma unroll
            for (int r = 0; r < 4; r++) acc[i][j][r] = 0.f;

    // Staging pointers: thread covers row (tid>>1), uint4 part (tid&1)
    const uint4* qxh = (const uint4*)(g_Xh + ((size_t)b * TVAL + t0 + (tid >> 1)) * DVAL);
    const uint4* qxl = (const uint4*)(g_Xl + ((size_t)b * TVAL + t0 + (tid >> 1)) * DVAL);
    const uint4* qeh = (const uint4*)(g_Eh + (size_t)(k0 + (tid >> 1)) * DVAL);
    const uint4* qel = (const uint4*)(g_El + (size_t)(k0 + (tid >> 1)) * DVAL);
    const int qoff = (tid & 1);
    const int soff = (tid >> 1) * 32 + (tid & 1) * 16;

    const uint32_t smb = smem_u32(sbuf);
    // lane-constant ldmatrix offsets
    const uint32_t aoff = (uint32_t)((tw * 32 + (l & 15)) * 32 + (l >> 4) * 16);
    const uint32_t boff = (uint32_t)(8192 + (kw * 64 + ((l >> 4) & 1) * 8 + (l & 7)) * 32 +
                                     ((l >> 3) & 1) * 16);

    // preload chunk 0
    uint4 rAh = qxh[qoff], rAl = qxl[qoff], rBh = qeh[qoff], rBl = qel[qoff];
    *(uint4*)(sbuf[0] + soff)         = rAh;
    *(uint4*)(sbuf[0] + 4096 + soff)  = rAl;
    *(uint4*)(sbuf[0] + 8192 + soff)  = rBh;
    *(uint4*)(sbuf[0] + 12288 + soff) = rBl;
    __syncthreads();

    for (int c = 0; c < 16; c++) {
        if (c < 15) {
            int q = (c + 1) * 2 + qoff;
            rAh = qxh[q]; rAl = qxl[q]; rBh = qeh[q]; rBl = qel[q];
        }
        const uint32_t sb32 = smb + (uint32_t)((c & 1) * 16384);
        #pragma unroll
        for (int h = 0; h < 2; h++) {
            uint32_t a0r[4], a1r[4];
            ldsm4(a0r, sb32 + (uint32_t)(h * 4096) + aoff);
            ldsm4(a1r, sb32 + (uint32_t)(h * 4096) + aoff + 512);
            #pragma unroll
            for (int g = 0; g < 2; g++) {
                #pragma unroll
                for (int p = 0; p < 4; p++) {
                    uint32_t br[4];
                    ldsm4(br, sb32 + (uint32_t)(g * 4096) + boff + (uint32_t)(p * 512));
                    MMA16816(acc[0][2 * p],     a0r, br[0], br[1]);
                    MMA16816(acc[0][2 * p + 1], a0r, br[2], br[3]);
                    MMA16816(acc[1][2 * p],     a1r, br[0], br[1]);
                    MMA16816(acc[1][2 * p + 1], a1r, br[2], br[3]);
                }
            }
        }
        if (c < 15) {
            char* d = sbuf[(c + 1) & 1];
            *(uint4*)(d + soff)         = rAh;
            *(uint4*)(d + 4096 + soff)  = rAl;
            *(uint4*)(d + 8192 + soff)  = rBh;
            *(uint4*)(d + 12288 + soff) = rBl;
            __syncthreads();
        }
    }

    // Epilogue: per-thread rows; top-2 per row over this warp's 64 k's.
    #pragma unroll
    for (int mt = 0; mt < 2; mt++) {
        #pragma unroll
        for (int rh = 0; rh < 2; rh++) {
            int row = tw * 32 + mt * 16 + rh * 8 + (l >> 2);
            float sx = g_xnorm[(size_t)b * TVAL + t0 + row];
            u64 m1 = ~0ull, m2 = ~0ull;
            #pragma unroll
            for (int nt = 0; nt < 8; nt++) {
                #pragma unroll
                for (int e = 0; e < 2; e++) {
                    float M = acc[mt][nt][rh * 2 + e];
                    int kl = kw * 64 + nt * 8 + (l & 3) * 2 + e;
                    float s = __fadd_rn(sx, en_sm[kl]);
                    float dist = __fmaf_rn(NEG2POW9, M, s);
                    u64 key = ((u64)ford(dist) << 32) | (unsigned)(k0 + kl);
                    if (key < m1) { m2 = m1; m1 = key; }
                    else if (key < m2) { m2 = key; }
                }
            }
            #pragma unroll
            for (int off = 1; off <= 2; off++) {  // quad reduce (lanes share row)
                u64 o1 = __shfl_xor_sync(0xffffffffu, m1, off);
                u64 o2 = __shfl_xor_sync(0xffffffffu, m2, off);
                u64 a  = (m1 < o1) ? m1 : o1;
                u64 bm = (m1 < o1) ? o1 : m1;
                u64 cn = (m2 < o2) ? m2 : o2;
                m1 = a;
                m2 = (bm < cn) ? bm : cn;
            }
            if ((l & 3) == 0) { cand_sm[row][kw][0] = m1; cand_sm[row][kw][1] = m2; }
        }
    }
    __syncthreads();

    if (tid < 128) {
        u64 a1 = cand_sm[tid][0][0], a2 = cand_sm[tid][0][1];
        u64 b1 = cand_sm[tid][1][0], b2 = cand_sm[tid][1][1];
        u64 M1 = (a1 < b1) ? a1 : b1;
        u64 hiMin = (a1 < b1) ? b1 : a1;
        u64 loSec = (a2 < b2) ? a2 : b2;
        u64 M2 = (hiMin < loSec) ? hiMin : loSec;
        size_t r = ((size_t)b * TVAL + t0 + tid) * 16 + (size_t)blockIdx.x * 2;
        g_cand[r] = M1;
        g_cand[r + 1] = M2;
    }
}

// Fixup: exact fp32 rescore of near-tie candidates; writes final index.
__global__ void fixup_kernel(const float* __restrict__ X, const float* __restrict__ E) {
    const unsigned FULL = 0xffffffffu;
    int gw = (blockIdx.x * 256 + threadIdx.x) >> 5;
    int lane = threadIdx.x & 31;
    if (gw >= NVAL) return;

    u64 key = ~0ull;
    if (lane < 16) key = g_cand[(size_t)gw * 16 + lane];
    u64 m = key;
    #pragma unroll
    for (int o = 16; o; o >>= 1) {
        u64 v = __shfl_xor_sync(FULL, m, o);
        m = (v < m) ? v : m;
    }
    unsigned minord = (unsigned)(m >> 32);
    bool flag = (lane < 16) && ((unsigned)(key >> 32) <= minord + 3u);
    unsigned mask = __ballot_sync(FULL, flag);
    int winner;
    if (__popc(mask) <= 1) {
        winner = (int)(unsigned)(m & 0xffffffffu);
    } else {
        int b = gw >> 11, t = gw & (TVAL - 1);
        float sx = g_xnorm[gw];
        const float* xb = X + (size_t)b * DVAL * TVAL + t;
        u64 best = ~0ull;
        unsigned mm = mask;
        while (mm) {
            int src = __ffs(mm) - 1;
            mm &= mm - 1;
            int k = (int)(unsigned)(__shfl_sync(FULL, key, src) & 0xffffffffu);
            const float* er = E + (size_t)k * DVAL;
            float p = 0.f;
            #pragma unroll
            for (int d = lane; d < DVAL; d += 32) p += xb[(size_t)d * TVAL] * er[d];
            #pragma unroll
            for (int o = 16; o; o >>= 1) p += __shfl_xor_sync(FULL, p, o);
            float s = __fadd_rn(sx, g_enorm[k]);
            float dist = __fmaf_rn(-2.0f, p, s);
            u64 k2 = ((u64)ford(dist) << 32) | (unsigned)k;
            best = (k2 < best) ? k2 : best;
        }
        winner = (int)(unsigned)(best & 0xffffffffu);
    }
    if (lane == 0) g_idx[gw] = winner;
}

// Gather + straight-through output + indices + loss partials
__global__ void gather_out_kernel(const float* __restrict__ X,
                                  const float* __restrict__ E,
                                  float* __restrict__ out) {
    const int tid = threadIdx.x;
    const int b = blockIdx.y;
    const int t = blockIdx.x * 256 + tid;

    int idx = g_idx[(size_t)b * TVAL + t];
    const float* erow = E + (size_t)idx * DVAL;

    float s = 0.f;
    size_t base = (size_t)b * DVAL * TVAL + t;
    for (int d = 0; d < DVAL; d++) {
        float q = erow[d];
        float xv = X[base + (size_t)d * TVAL];
        float diff = __fadd_rn(q, -xv);
        out[base + (size_t)d * TVAL] = __fadd_rn(xv, diff);
        s += diff * diff;
    }
    out[(size_t)QELEMS + 1 + (size_t)b * TVAL + t] = (float)idx;

    __shared__ float r[256];
    r[tid] = s;
    __syncthreads();
    #pragma unroll
    for (int o = 128; o; o >>= 1) {
        if (tid < o) r[tid] += r[tid + o];
        __syncthreads();
    }
    if (tid == 0) g_partials[blockIdx.y * (TVAL / 256) + blockIdx.x] = r[0];
}

__global__ void finalize_kernel(float* __restrict__ out) {
    __shared__ float r[256];
    int tid = threadIdx.x;
    r[tid] = g_partials[tid];
    __syncthreads();
    #pragma unroll
    for (int o = 128; o; o >>= 1) {
        if (tid < o) r[tid] += r[tid + o];
        __syncthreads();
    }
    if (tid == 0) out[QELEMS] = 1.25f * (r[0] / (float)QELEMS);
}

extern "C" void kernel_launch(void* const* d_in, const int* in_sizes, int n_in,
                              void* d_out, int out_size) {
    const float* X = (const float*)d_in[0];  // inputs [B, D, T] fp32
    const float* E = (const float*)d_in[1];  // embeddings [K, D] fp32
    float* out = (float*)d_out;              // [quantized | loss | indices] fp32

    prep_e_kernel<<<(KVAL * DVAL) / 256, 256>>>(E);
    prep_x_kernel<<<dim3(TVAL / 32, DVAL / 32, BVAL), dim3(32, 8)>>>(X);
    enorm_kernel<<<KVAL / 8, 256>>>(E);
    xnorm_kernel<<<dim3(TVAL / 256, BVAL), 256>>>(X);
    dist_tc_kernel<<<dim3(KTILES, TVAL / 128, BVAL), 256>>>();
    fixup_kernel<<<NVAL / 8, 256>>>(X, E);
    gather_out_kernel<<<dim3(TVAL / 256, BVAL), 256>>>(X, E, out);
    finalize_kernel<<<1, 256>>>(out);
}

// round 17
// speedup vs baseline: 1.8613x; 1.1759x over previous
#include <cuda_runtime.h>
#include <cuda_fp16.h>
#include <cstdint>

// Problem constants (fixed: B=32, D=256, T=2048, K=1024)
#define BVAL 32
#define DVAL 256
#define TVAL 2048
#define KVAL 1024
#define NVAL (BVAL * TVAL)          // 65536 vectors
#define QELEMS (BVAL * DVAL * TVAL) // 16777216 quantized elements
#define NPART (BVAL * (TVAL / 256) * 4) // 1024 loss partials (4-way d-split)
#define KTILES (KVAL / 128)         // 8

typedef unsigned long long u64;

__device__ float g_enorm[KVAL];
__device__ float g_xnorm[NVAL];
__device__ float g_partials[NPART];
__device__ u64   g_cand[(size_t)NVAL * 16]; // [row][ktile(8)][2]
__device__ int   g_idx[NVAL];
// Pre-split operands (halves). X transposed to [B][T][D] (d-contiguous).
__device__ __half g_Xh[QELEMS];
__device__ __half g_Xl[QELEMS];
__device__ __half g_Eh[KVAL * DVAL];
__device__ __half g_El[KVAL * DVAL];

// dist = s - 2*(M/1024) = fmaf(-2^-9, M, s), since E was scaled by 1024
#define NEG2POW9 (-0.001953125f)

__device__ __forceinline__ unsigned int ford(float f) {
    unsigned int b = __float_as_uint(f);
    return (b & 0x80000000u) ? ~b : (b | 0x80000000u);
}
__device__ __forceinline__ uint32_t smem_u32(const void* p) {
    uint32_t a;
    asm("{ .reg .u64 t; cvta.to.shared.u64 t, %1; cvt.u32.u64 %0, t; }"
        : "=r"(a) : "l"(p));
    return a;
}
__device__ __forceinline__ void ldsm4(uint32_t* r, uint32_t addr) {
    asm volatile("ldmatrix.sync.aligned.m8n8.x4.shared.b16 {%0,%1,%2,%3}, [%4];"
                 : "=r"(r[0]), "=r"(r[1]), "=r"(r[2]), "=r"(r[3]) : "r"(addr));
}
#define MMA16816(d, a, b0, b1)                                                \
    asm volatile("mma.sync.aligned.m16n8k16.row.col.f32.f16.f16.f32 "         \
                 "{%0,%1,%2,%3},{%4,%5,%6,%7},{%8,%9},{%0,%1,%2,%3};"         \
                 : "+f"((d)[0]), "+f"((d)[1]), "+f"((d)[2]), "+f"((d)[3])     \
                 : "r"((a)[0]), "r"((a)[1]), "r"((a)[2]), "r"((a)[3]),        \
                   "r"(b0), "r"(b1))

// ---------------- prep: split E (scaled by 1024) into hi/lo halves ----------
__global__ void prep_e_kernel(const float* __restrict__ E) {
    int i = blockIdx.x * 256 + threadIdx.x;
    float e = E[i] * 1024.0f;                 // exact pow2 scale
    __half h = __float2half_rn(e);
    g_Eh[i] = h;
    g_El[i] = __float2half_rn(e - __half2float(h));
}

// ---------------- prep: transpose X to [B][T][D] and split hi/lo ------------
__global__ void prep_x_kernel(const float* __restrict__ X) {
    __shared__ float tile[32][33];
    const int b = blockIdx.z, d0 = blockIdx.y * 32, t0 = blockIdx.x * 32;
    const int tx = threadIdx.x, ty = threadIdx.y;  // (32, 8)
    #pragma unroll
    for (int r = 0; r < 4; r++) {
        int d = r * 8 + ty;
        tile[d][tx] = X[(size_t)b * DVAL * TVAL + (size_t)(d0 + d) * TVAL + t0 + tx];
    }
    __syncthreads();
    #pragma unroll
    for (int r = 0; r < 4; r++) {
        int t = r * 8 + ty;
        float v = tile[tx][t];                 // tx indexes d now
        __half h = __float2half_rn(v);
        size_t o = ((size_t)b * TVAL + t0 + t) * DVAL + d0 + tx;
        g_Xh[o] = h;
        g_Xl[o] = __float2half_rn(v - __half2float(h));
    }
}

// ||e_k||^2 exact (double accum -> fp32; tiny kernel, K=1024 rows)
__global__ void enorm_kernel(const float* __restrict__ E) {
    int warp = threadIdx.x >> 5, lane = threadIdx.x & 31;
    int k = blockIdx.x * 8 + warp;
    if (k >= KVAL) return;
    const float* row = E + (size_t)k * DVAL;
    double s = 0.0;
    for (int d = lane; d < DVAL; d += 32) { double v = (double)row[d]; s += v * v; }
    #pragma unroll
    for (int o = 16; o; o >>= 1) s += __shfl_xor_sync(0xffffffffu, s, o);
    if (lane == 0) g_enorm[k] = (float)s;
}

// ||x_n||^2 per vector: fp32, 8 independent accumulators + fixed pairwise tree
// (deterministic; sxx enters all of a row's distances uniformly, and fixup
// rescores near-ties with this same value -> argmin-safe).
__global__ void xnorm_kernel(const float* __restrict__ X) {
    int t = blockIdx.x * 256 + threadIdx.x;
    int b = blockIdx.y;
    const float* base = X + (size_t)b * DVAL * TVAL + t;
    float a[8];
    #pragma unroll
    for (int j = 0; j < 8; j++) a[j] = 0.f;
    #pragma unroll 4
    for (int d0 = 0; d0 < DVAL; d0 += 8) {
        #pragma unroll
        for (int j = 0; j < 8; j++) {
            float v = base[(size_t)(d0 + j) * TVAL];
            a[j] = __fmaf_rn(v, v, a[j]);
        }
    }
    float s01 = __fadd_rn(a[0], a[1]), s23 = __fadd_rn(a[2], a[3]);
    float s45 = __fadd_rn(a[4], a[5]), s67 = __fadd_rn(a[6], a[7]);
    float s = __fadd_rn(__fadd_rn(s01, s23), __fadd_rn(s45, s67));
    g_xnorm[(size_t)b * TVAL + t] = s;
}

// ---------------- distance GEMM via mma.sync (HMMA) + top-2 epilogue -------
// CTA tile: 128 t x 128 k, D in 16 chunks of 16. 8 warps: tw=wid&3 (t-group
// of 32 rows), kw=wid>>2 (k-group of 64 cols). 3 split passes (hh, hl, lh);
// the ll pass contributes ~6e-9 to distances (grid ulp 3e-5) and is dropped.
__global__ __launch_bounds__(256, 2)
void dist_tc_kernel() {
    __shared__ __align__(128) char sbuf[2][16384]; // per buf: Ah|Al|Bh|Bl (4KB each)
    __shared__ float en_sm[128];
    __shared__ u64 cand_sm[128][2][2];

    const int tid = threadIdx.x, wid = tid >> 5, l = tid & 31;
    const int tw = wid & 3, kw = wid >> 2;
    const int k0 = blockIdx.x * 128, t0 = blockIdx.y * 128, b = blockIdx.z;

    if (tid < 128) en_sm[tid] = g_enorm[k0 + tid];

    float acc[2][8][4];
    #pragma unroll
    for (int i = 0; i < 2; i++)
        #pragma unroll
        for (int j = 0; j < 8; j++)
            #pragma unroll
            for (int r = 0; r < 4; r++) acc[i][j][r] = 0.f;

    // Staging pointers: thread covers row (tid>>1), uint4 part (tid&1)
    const uint4* qxh = (const uint4*)(g_Xh + ((size_t)b * TVAL + t0 + (tid >> 1)) * DVAL);
    const uint4* qxl = (const uint4*)(g_Xl + ((size_t)b * TVAL + t0 + (tid >> 1)) * DVAL);
    const uint4* qeh = (const uint4*)(g_Eh + (size_t)(k0 + (tid >> 1)) * DVAL);
    const uint4* qel = (const uint4*)(g_El + (size_t)(k0 + (tid >> 1)) * DVAL);
    const int qoff = (tid & 1);
    const int soff = (tid >> 1) * 32 + (tid & 1) * 16;

    const uint32_t smb = smem_u32(sbuf);
    // lane-constant ldmatrix offsets
    const uint32_t aoff = (uint32_t)((tw * 32 + (l & 15)) * 32 + (l >> 4) * 16);
    const uint32_t boff = (uint32_t)(8192 + (kw * 64 + ((l >> 4) & 1) * 8 + (l & 7)) * 32 +
                                     ((l >> 3) & 1) * 16);

    // preload chunk 0
    uint4 rAh = qxh[qoff], rAl = qxl[qoff], rBh = qeh[qoff], rBl = qel[qoff];
    *(uint4*)(sbuf[0] + soff)         = rAh;
    *(uint4*)(sbuf[0] + 4096 + soff)  = rAl;
    *(uint4*)(sbuf[0] + 8192 + soff)  = rBh;
    *(uint4*)(sbuf[0] + 12288 + soff) = rBl;
    __syncthreads();

    for (int c = 0; c < 16; c++) {
        if (c < 15) {
            int q = (c + 1) * 2 + qoff;
            rAh = qxh[q]; rAl = qxl[q]; rBh = qeh[q]; rBl = qel[q];
        }
        const uint32_t sb32 = smb + (uint32_t)((c & 1) * 16384);
        #pragma unroll
        for (int h = 0; h < 2; h++) {
            uint32_t a0r[4], a1r[4];
            ldsm4(a0r, sb32 + (uint32_t)(h * 4096) + aoff);
            ldsm4(a1r, sb32 + (uint32_t)(h * 4096) + aoff + 512);
            #pragma unroll
            for (int g = 0; g < 2; g++) {
                if (h == 1 && g == 1) continue;   // skip ll pass (negligible)
                #pragma unroll
                for (int p = 0; p < 4; p++) {
                    uint32_t br[4];
                    ldsm4(br, sb32 + (uint32_t)(g * 4096) + boff + (uint32_t)(p * 512));
                    MMA16816(acc[0][2 * p],     a0r, br[0], br[1]);
                    MMA16816(acc[0][2 * p + 1], a0r, br[2], br[3]);
                    MMA16816(acc[1][2 * p],     a1r, br[0], br[1]);
                    MMA16816(acc[1][2 * p + 1], a1r, br[2], br[3]);
                }
            }
        }
        if (c < 15) {
            char* d = sbuf[(c + 1) & 1];
            *(uint4*)(d + soff)         = rAh;
            *(uint4*)(d + 4096 + soff)  = rAl;
            *(uint4*)(d + 8192 + soff)  = rBh;
            *(uint4*)(d + 12288 + soff) = rBl;
            __syncthreads();
        }
    }

    // Epilogue: per-thread rows; top-2 per row over this warp's 64 k's.
    #pragma unroll
    for (int mt = 0; mt < 2; mt++) {
        #pragma unroll
        for (int rh = 0; rh < 2; rh++) {
            int row = tw * 32 + mt * 16 + rh * 8 + (l >> 2);
            float sx = g_xnorm[(size_t)b * TVAL + t0 + row];
            u64 m1 = ~0ull, m2 = ~0ull;
            #pragma unroll
            for (int nt = 0; nt < 8; nt++) {
                #pragma unroll
                for (int e = 0; e < 2; e++) {
                    float M = acc[mt][nt][rh * 2 + e];
                    int kl = kw * 64 + nt * 8 + (l & 3) * 2 + e;
                    float s = __fadd_rn(sx, en_sm[kl]);
                    float dist = __fmaf_rn(NEG2POW9, M, s);
                    u64 key = ((u64)ford(dist) << 32) | (unsigned)(k0 + kl);
                    if (key < m1) { m2 = m1; m1 = key; }
                    else if (key < m2) { m2 = key; }
                }
            }
            #pragma unroll
            for (int off = 1; off <= 2; off++) {  // quad reduce (lanes share row)
                u64 o1 = __shfl_xor_sync(0xffffffffu, m1, off);
                u64 o2 = __shfl_xor_sync(0xffffffffu, m2, off);
                u64 a  = (m1 < o1) ? m1 : o1;
                u64 bm = (m1 < o1) ? o1 : m1;
                u64 cn = (m2 < o2) ? m2 : o2;
                m1 = a;
                m2 = (bm < cn) ? bm : cn;
            }
            if ((l & 3) == 0) { cand_sm[row][kw][0] = m1; cand_sm[row][kw][1] = m2; }
        }
    }
    __syncthreads();

    if (tid < 128) {
        u64 a1 = cand_sm[tid][0][0], a2 = cand_sm[tid][0][1];
        u64 b1 = cand_sm[tid][1][0], b2 = cand_sm[tid][1][1];
        u64 M1 = (a1 < b1) ? a1 : b1;
        u64 hiMin = (a1 < b1) ? b1 : a1;
        u64 loSec = (a2 < b2) ? a2 : b2;
        u64 M2 = (hiMin < loSec) ? hiMin : loSec;
        size_t r = ((size_t)b * TVAL + t0 + tid) * 16 + (size_t)blockIdx.x * 2;
        g_cand[r] = M1;
        g_cand[r + 1] = M2;
    }
}

// Fixup: exact fp32 rescore of near-tie candidates; writes final index.
__global__ void fixup_kernel(const float* __restrict__ X, const float* __restrict__ E) {
    const unsigned FULL = 0xffffffffu;
    int gw = (blockIdx.x * 256 + threadIdx.x) >> 5;
    int lane = threadIdx.x & 31;
    if (gw >= NVAL) return;

    u64 key = ~0ull;
    if (lane < 16) key = g_cand[(size_t)gw * 16 + lane];
    u64 m = key;
    #pragma unroll
    for (int o = 16; o; o >>= 1) {
        u64 v = __shfl_xor_sync(FULL, m, o);
        m = (v < m) ? v : m;
    }
    unsigned minord = (unsigned)(m >> 32);
    bool flag = (lane < 16) && ((unsigned)(key >> 32) <= minord + 3u);
    unsigned mask = __ballot_sync(FULL, flag);
    int winner;
    if (__popc(mask) <= 1) {
        winner = (int)(unsigned)(m & 0xffffffffu);
    } else {
        int b = gw >> 11, t = gw & (TVAL - 1);
        float sx = g_xnorm[gw];
        const float* xb = X + (size_t)b * DVAL * TVAL + t;
        u64 best = ~0ull;
        unsigned mm = mask;
        while (mm) {
            int src = __ffs(mm) - 1;
            mm &= mm - 1;
            int k = (int)(unsigned)(__shfl_sync(FULL, key, src) & 0xffffffffu);
            const float* er = E + (size_t)k * DVAL;
            float p = 0.f;
            #pragma unroll
            for (int d = lane; d < DVAL; d += 32) p += xb[(size_t)d * TVAL] * er[d];
            #pragma unroll
            for (int o = 16; o; o >>= 1) p += __shfl_xor_sync(FULL, p, o);
            float s = __fadd_rn(sx, g_enorm[k]);
            float dist = __fmaf_rn(-2.0f, p, s);
            u64 k2 = ((u64)ford(dist) << 32) | (unsigned)k;
            best = (k2 < best) ? k2 : best;
        }
        winner = (int)(unsigned)(best & 0xffffffffu);
    }
    if (lane == 0) g_idx[gw] = winner;
}

// Gather + straight-through output + indices + loss partials.
// 4-way d-split (grid z) for latency hiding: each thread covers 64 d's.
__global__ void gather_out_kernel(const float* __restrict__ X,
                                  const float* __restrict__ E,
                                  float* __restrict__ out) {
    const int tid = threadIdx.x;
    const int b = blockIdx.y;
    const int t = blockIdx.x * 256 + tid;
    const int dz = blockIdx.z;          // 0..3, d-range [dz*64, dz*64+64)

    int idx = g_idx[(size_t)b * TVAL + t];
    const float* erow = E + (size_t)idx * DVAL + dz * 64;

    float s = 0.f;
    size_t base = (size_t)b * DVAL * TVAL + (size_t)dz * 64 * TVAL + t;
    #pragma unroll 8
    for (int d = 0; d < 64; d++) {
        float q = erow[d];
        float xv = X[base + (size_t)d * TVAL];
        float diff = __fadd_rn(q, -xv);
        out[base + (size_t)d * TVAL] = __fadd_rn(xv, diff);
        s = __fmaf_rn(diff, diff, s);
    }
    if (dz == 0)
        out[(size_t)QELEMS + 1 + (size_t)b * TVAL + t] = (float)idx;

    __shared__ float r[256];
    r[tid] = s;
    __syncthreads();
    #pragma unroll
    for (int o = 128; o; o >>= 1) {
        if (tid < o) r[tid] += r[tid + o];
        __syncthreads();
    }
    if (tid == 0)
        g_partials[((size_t)blockIdx.y * (TVAL / 256) + blockIdx.x) * 4 + dz] = r[0];
}

__global__ void finalize_kernel(float* __restrict__ out) {
    __shared__ float r[256];
    int tid = threadIdx.x;
    // fixed order: 4 sequential adds per thread, then tree -> deterministic
    float s = 0.f;
    #pragma unroll
    for (int j = 0; j < 4; j++) s = __fadd_rn(s, g_partials[tid * 4 + j]);
    r[tid] = s;
    __syncthreads();
    #pragma unroll
    for (int o = 128; o; o >>= 1) {
        if (tid < o) r[tid] += r[tid + o];
        __syncthreads();
    }
    if (tid == 0) out[QELEMS] = 1.25f * (r[0] / (float)QELEMS);
}

extern "C" void kernel_launch(void* const* d_in, const int* in_sizes, int n_in,
                              void* d_out, int out_size) {
    const float* X = (const float*)d_in[0];  // inputs [B, D, T] fp32
    const float* E = (const float*)d_in[1];  // embeddings [K, D] fp32
    float* out = (float*)d_out;              // [quantized | loss | indices] fp32

    prep_e_kernel<<<(KVAL * DVAL) / 256, 256>>>(E);
    prep_x_kernel<<<dim3(TVAL / 32, DVAL / 32, BVAL), dim3(32, 8)>>>(X);
    enorm_kernel<<<KVAL / 8, 256>>>(E);
    xnorm_kernel<<<dim3(TVAL / 256, BVAL), 256>>>(X);
    dist_tc_kernel<<<dim3(KTILES, TVAL / 128, BVAL), 256>>>();
    fixup_kernel<<<NVAL / 8, 256>>>(X, E);
    gather_out_kernel<<<dim3(TVAL / 256, BVAL, 4), 256>>>(X, E, out);
    finalize_kernel<<<1, 256>>>(out);
}